// round 10
// baseline (speedup 1.0000x reference)
#include <cuda_runtime.h>
#include <math.h>

// B=16, K=16 steps, N=1024, D=256, L=8.  Rows = B*L = 128.  16 n-chunks of 64.
#define S_ELEMS (16*16*8*256)
#define QT_PLANE (128*1024)
#define GI_PLANE (128*768)
#define H1_PLANE (128*256)
#define UP_PLANE (128*256)
#define HPITCH 260

// ---------------- scratch ----------------
__device__ __align__(16) float g_slots[128*256];
__device__ __align__(16) float g_Mcomb[256*1024];   // [k][0:256]=Wq^T Wk*scale, [k][256:1024]=W_hh^T
__device__ __align__(16) float g_cpart[8*1024];     // 8 e-partials of [scale*bq@Wk | b_hh]
__device__ __align__(16) float g_M2[768*256];       // W_ih @ Wv
__device__ __align__(16) float g_c2part[8*768];     // 8 e-partials of (W_ih@bv + b_ih)
__device__ __align__(16) float g_qtgh2[2*QT_PLANE]; // 2 K-split partials of [Qt | gh]
__device__ __align__(16) float g_escore[128*1024];  // exp(score - chunkmax)
__device__ __align__(16) float g_pmax[128*16];
__device__ __align__(16) float g_psum[128*16];
__device__ __align__(16) float g_upart[16*UP_PLANE];// UNnormalized expP@H partials per n-chunk
__device__ __align__(16) float g_gi2[2*GI_PLANE];   // 2 K-split partials of gi
__device__ __align__(16) float g_s2[128*256];
__device__ __align__(16) float g_h1p[2*H1_PLANE];   // 2 K-split partials of ffn1 pre-activation

__device__ __forceinline__ float sigm(float x) { return 1.f / (1.f + expf(-x)); }

// ============ 32x32-tile GEMM body (precompute only) ============
template<int AT>
__device__ __forceinline__ void gemm_body(
    int m0, int c0,
    const float* __restrict__ A, int lda,
    const float* __restrict__ B, int ldb,
    float* __restrict__ C, int ldc, float alpha)
{
    __shared__ float As[32][33];
    __shared__ __align__(16) float Bs[32][36];
    const int tid = threadIdx.x;
    const int row = tid & 31, cg = tid >> 5;
    float a0 = 0.f, a1 = 0.f, a2 = 0.f, a3 = 0.f;
    for (int k0 = 0; k0 < 256; k0 += 32) {
        if (AT) {
            int r = tid & 31, e = tid >> 5;
            #pragma unroll
            for (int i = 0; i < 4; i++) { int ee = e + i*8; As[r][ee] = A[(size_t)(k0+ee)*lda + m0 + r]; }
        } else {
            int e = tid & 31, r = tid >> 5;
            #pragma unroll
            for (int i = 0; i < 4; i++) { int rr = r + i*8; As[rr][e] = A[(size_t)(m0+rr)*lda + k0 + e]; }
        }
        {
            int c = tid & 31, e = tid >> 5;
            #pragma unroll
            for (int i = 0; i < 4; i++) { int ee = e + i*8; Bs[ee][c] = B[(size_t)(k0+ee)*ldb + c0 + c]; }
        }
        __syncthreads();
        #pragma unroll
        for (int e = 0; e < 32; e++) {
            float a = As[row][e];
            float4 b4 = *(const float4*)&Bs[e][cg*4];
            a0 = fmaf(a,b4.x,a0); a1 = fmaf(a,b4.y,a1); a2 = fmaf(a,b4.z,a2); a3 = fmaf(a,b4.w,a3);
        }
        __syncthreads();
    }
    int cb = c0 + cg*4;
    *(float4*)&C[(size_t)(m0+row)*ldc + cb] = make_float4(a0*alpha, a1*alpha, a2*alpha, a3*alpha);
}

// ================= precompute (2 kernels) =================
__global__ void pre_misc(const float* __restrict__ eps, const float* __restrict__ mu,
                         const float* __restrict__ ls, const float* __restrict__ W_hh,
                         const float* __restrict__ bq, const float* __restrict__ Wk,
                         const float* __restrict__ b_hh, const float* __restrict__ W_ih,
                         const float* __restrict__ bv, const float* __restrict__ b_ih)
{
    const int bx = blockIdx.x, tid = threadIdx.x;
    if (bx < 128) {
        int i = bx * 256 + tid;
        int ld = i & 2047;
        g_slots[i] = mu[ld] + expf(ls[ld]) * eps[i];
    } else if (bx < 896) {
        int idx = (bx - 128) * 256 + tid;       // 256x768
        int c = idx >> 8, k = idx & 255;
        g_Mcomb[k * 1024 + 256 + c] = W_hh[c * 256 + k];
    } else if (bx < 928) {
        int q = bx - 896;
        int p = q >> 2;
        int c = (q & 3) * 256 + tid;
        if (c < 256) {
            int e0 = p * 32;
            float s = 0.f;
            #pragma unroll 8
            for (int e = 0; e < 32; e++) s = fmaf(bq[e0+e], Wk[(e0+e)*256 + c], s);
            g_cpart[p * 1024 + c] = s * 0.0625f;
        } else {
            g_cpart[p * 1024 + c] = (p == 0) ? b_hh[c - 256] : 0.f;
        }
    } else {
        int q = bx - 928;
        int p = q / 3;
        int c = (q % 3) * 256 + tid;
        int e0 = p * 32;
        float s = (p == 0) ? b_ih[c] : 0.f;
        #pragma unroll 8
        for (int e = 0; e < 32; e++) s = fmaf(W_ih[c*256 + e0+e], bv[e0+e], s);
        g_c2part[p * 768 + c] = s;
    }
}

__global__ void pre_gemm(const float* __restrict__ Wq, const float* __restrict__ Wk,
                         const float* __restrict__ W_ih, const float* __restrict__ Wv)
{
    if (blockIdx.y < 8)
        gemm_body<1>(blockIdx.y*32, blockIdx.x*32, Wq,256, Wk,256, g_Mcomb,1024, 0.0625f);
    else
        gemm_body<0>((blockIdx.y-8)*32, blockIdx.x*32, W_ih,256, Wv,256, g_M2,256, 1.f);
}

// ================= per-step kernels (5) =================

// qtgh partials: grid (32 colT, 8 rowT, 2 ksplit), 128 thr, tile 16x32.
__global__ void k_qtgh()
{
    __shared__ float As[16][33];
    __shared__ __align__(16) float Bs[32][36];
    const int tid = threadIdx.x;
    const int m0 = blockIdx.y * 16, c0 = blockIdx.x * 32, kb = blockIdx.z * 128;
    const int row = tid & 15, cg = tid >> 4;
    float a0=0.f, a1=0.f, a2=0.f, a3=0.f;
    for (int k0 = 0; k0 < 128; k0 += 32) {
        { int e = tid & 31, r = tid >> 5;
          #pragma unroll
          for (int i = 0; i < 4; i++) { int rr = r + i*4; As[rr][e] = g_slots[(m0+rr)*256 + kb + k0 + e]; } }
        { int c = tid & 31, e = tid >> 5;
          #pragma unroll
          for (int i = 0; i < 8; i++) { int ee = e + i*4; Bs[ee][c] = g_Mcomb[(size_t)(kb+k0+ee)*1024 + c0 + c]; } }
        __syncthreads();
        #pragma unroll
        for (int e = 0; e < 32; e++) {
            float a = As[row][e];
            float4 b4 = *(const float4*)&Bs[e][cg*4];
            a0 = fmaf(a,b4.x,a0); a1 = fmaf(a,b4.y,a1); a2 = fmaf(a,b4.z,a2); a3 = fmaf(a,b4.w,a3);
        }
        __syncthreads();
    }
    int cb = c0 + cg*4;
    if (blockIdx.z == 0) {
        #pragma unroll
        for (int p = 0; p < 8; p++) {
            const float* bp = g_cpart + p * 1024;
            a0 += bp[cb]; a1 += bp[cb+1]; a2 += bp[cb+2]; a3 += bp[cb+3];
        }
    }
    *(float4*)&g_qtgh2[(size_t)blockIdx.z*QT_PLANE + (m0+row)*1024 + cb] = make_float4(a0,a1,a2,a3);
}

// Fused scores + chunk softmax stats + unnormalized expP@H partials.
// grid (16 nchunk, 16 b), 256 thr.  Dynamic smem: H tile staged ONCE (one DRAM read of H/step).
__global__ void scoresU_kernel(const float* __restrict__ H, int t)
{
    extern __shared__ float sm[];
    float* Hs    = sm;                 // 64 rows * HPITCH
    float* Qs    = sm + 64*HPITCH;     // 8 * 256
    float* attnS = Qs + 2048;          // 8 * 64
    float* redM  = attnS + 512;        // 8 * 2
    float* redS  = redM + 16;          // 8 * 2
    float* mrow  = redS + 16;          // 8

    const int b = blockIdx.y, chunk = blockIdx.x;
    const int n0 = chunk * 64;
    const int tid = threadIdx.x;
    const int nl = tid & 63, sg = tid >> 6;      // sg 0..3, 2 slots each
    const int lane = tid & 31;

    // Q = sum of 2 qtgh k-partials (first 256 cols)
    for (int i = tid; i < 512; i += 256) {
        int s = i >> 6, d4 = i & 63;
        float4 x0 = ((const float4*)(g_qtgh2 + (size_t)(b*8+s)*1024))[d4];
        float4 x1 = ((const float4*)(g_qtgh2 + QT_PLANE + (size_t)(b*8+s)*1024))[d4];
        ((float4*)Qs)[s*64 + d4] = make_float4(x0.x+x1.x, x0.y+x1.y, x0.z+x1.z, x0.w+x1.w);
    }
    // Stage H tile: 64 rows x 256 cols, pitch HPITCH
    const float* hb = H + ((size_t)(b*16 + t) * 1024 + n0) * 256;
    for (int i = tid; i < 4096; i += 256) {
        int r = i >> 6, c4 = i & 63;
        float4 v = ((const float4*)(hb + (size_t)r * 256))[c4];
        *(float4*)&Hs[r*HPITCH + c4*4] = v;
    }
    __syncthreads();

    // Phase 1: scores for 2 slots per thread over its n
    float a[2] = {0.f, 0.f};
    #pragma unroll 8
    for (int d = 0; d < 256; d += 4) {
        float4 h4 = *(const float4*)&Hs[nl*HPITCH + d];
        #pragma unroll
        for (int i = 0; i < 2; i++) {
            float4 q4 = *(const float4*)&Qs[(sg*2+i)*256 + d];
            a[i] = fmaf(h4.x,q4.x,a[i]); a[i] = fmaf(h4.y,q4.y,a[i]);
            a[i] = fmaf(h4.z,q4.z,a[i]); a[i] = fmaf(h4.w,q4.w,a[i]);
        }
    }
    // chunk-local max (64 values = 2 warps per slot-pair owner)
    #pragma unroll
    for (int i = 0; i < 2; i++) {
        float m = a[i];
        #pragma unroll
        for (int o = 16; o > 0; o >>= 1) m = fmaxf(m, __shfl_xor_sync(0xffffffffu, m, o));
        if (lane == 0) redM[(sg*2+i)*2 + (nl >> 5)] = m;
    }
    __syncthreads();
    if (tid < 8) {
        float m = fmaxf(redM[tid*2], redM[tid*2+1]);
        mrow[tid] = m;
        g_pmax[(b*8 + tid) * 16 + chunk] = m;
    }
    __syncthreads();
    #pragma unroll
    for (int i = 0; i < 2; i++) {
        float e = expf(a[i] - mrow[sg*2+i]);
        g_escore[(size_t)(b*8 + sg*2+i) * 1024 + n0 + nl] = e;
        attnS[(sg*2+i)*64 + nl] = e;
        #pragma unroll
        for (int o = 16; o > 0; o >>= 1) e += __shfl_xor_sync(0xffffffffu, e, o);
        if (lane == 0) redS[(sg*2+i)*2 + (nl >> 5)] = e;
    }
    __syncthreads();
    if (tid < 8) g_psum[(b*8 + tid) * 16 + chunk] = redS[tid*2] + redS[tid*2+1];

    // Phase 2: upart[s][j] = sum_n expP[s][n] * H[n][j]  (H from smem — no 2nd DRAM read)
    float acc[8] = {0.f,0.f,0.f,0.f,0.f,0.f,0.f,0.f};
    #pragma unroll 4
    for (int n = 0; n < 64; n++) {
        float hv = Hs[n*HPITCH + tid];
        #pragma unroll
        for (int s = 0; s < 8; s++) acc[s] = fmaf(attnS[s*64 + n], hv, acc[s]);
    }
    float* up = g_upart + (size_t)chunk * UP_PLANE;
    #pragma unroll
    for (int s = 0; s < 8; s++) up[(b*8 + s) * 256 + tid] = acc[s];
}

// gi partials: (flash-weighted sum of 16 upart planes) @ M2^T (+c2 on ks0).
// grid (24 colT, 8 rowT, 2 ks), 128 thr, tile 16x32.
__global__ void k_gi()
{
    __shared__ float As[16][33];
    __shared__ __align__(16) float Bs[32][36];
    __shared__ float sm_w[16][17];
    const int tid = threadIdx.x;
    const int m0 = blockIdx.y * 16, c0 = blockIdx.x * 32, kb = blockIdx.z * 128;
    const int row = tid & 15, cg = tid >> 4;

    if (tid < 16) {
        int r = m0 + tid;
        float m = g_pmax[r*16];
        #pragma unroll
        for (int c = 1; c < 16; c++) m = fmaxf(m, g_pmax[r*16 + c]);
        float S = 0.f;
        #pragma unroll
        for (int c = 0; c < 16; c++) S += g_psum[r*16 + c] * expf(g_pmax[r*16 + c] - m);
        float invS = 1.f / S;
        #pragma unroll
        for (int c = 0; c < 16; c++) sm_w[tid][c] = expf(g_pmax[r*16 + c] - m) * invS;
    }
    __syncthreads();

    float a0=0.f, a1=0.f, a2=0.f, a3=0.f;
    for (int k0 = 0; k0 < 128; k0 += 32) {
        { int e = tid & 31, r = tid >> 5;
          #pragma unroll
          for (int i = 0; i < 4; i++) {
              int rr = r + i*4;
              size_t idx = (size_t)(m0+rr)*256 + kb + k0 + e;
              float v = 0.f;
              #pragma unroll
              for (int p = 0; p < 16; p++)
                  v = fmaf(g_upart[idx + (size_t)p * UP_PLANE], sm_w[rr][p], v);
              As[rr][e] = v;
          } }
        { int e = tid & 31, c = tid >> 5;
          #pragma unroll
          for (int i = 0; i < 8; i++) { int cc = c + i*4; Bs[e][cc] = g_M2[(size_t)(c0+cc)*256 + kb + k0 + e]; } }
        __syncthreads();
        #pragma unroll
        for (int e = 0; e < 32; e++) {
            float a = As[row][e];
            float4 b4 = *(const float4*)&Bs[e][cg*4];
            a0 = fmaf(a,b4.x,a0); a1 = fmaf(a,b4.y,a1); a2 = fmaf(a,b4.z,a2); a3 = fmaf(a,b4.w,a3);
        }
        __syncthreads();
    }
    int cb = c0 + cg*4;
    if (blockIdx.z == 0) {
        #pragma unroll
        for (int p = 0; p < 8; p++) {
            const float* bp = g_c2part + p * 768;
            a0 += bp[cb]; a1 += bp[cb+1]; a2 += bp[cb+2]; a3 += bp[cb+3];
        }
    }
    *(float4*)&g_gi2[(size_t)blockIdx.z*GI_PLANE + (m0+row)*768 + cb] = make_float4(a0,a1,a2,a3);
}

// ffn1 with fused GRU + Beta writer.  grid (8 colT, 8 rowT, 2 ks) = 128 blocks, 128 thr.
__global__ void ffn1_gru_kernel(const float* __restrict__ W1, const float* __restrict__ b1,
                                float* __restrict__ beta, int t)
{
    __shared__ float As[16][33];
    __shared__ __align__(16) float Bs[32][36];
    const int tid = threadIdx.x;
    const int m0 = blockIdx.y * 16, c0 = blockIdx.x * 32, kb = blockIdx.z * 128;
    const int row = tid & 15, cg = tid >> 4;

    // ---- Beta writer: this block normalizes+writes row r = linear block id ----
    {
        int r = blockIdx.z * 64 + blockIdx.y * 8 + blockIdx.x;   // 0..127
        float m = g_pmax[r*16];
        #pragma unroll
        for (int c = 1; c < 16; c++) m = fmaxf(m, g_pmax[r*16 + c]);
        float S = 0.f;
        #pragma unroll
        for (int c = 0; c < 16; c++) S += g_psum[r*16 + c] * expf(g_pmax[r*16 + c] - m);
        float w = expf(g_pmax[r*16 + (tid >> 3)] - m) / S;       // cols tid*8.. in chunk tid>>3
        const float4* e4 = (const float4*)(g_escore + (size_t)r * 1024 + tid * 8);
        int bb = r >> 3, l = r & 7;
        float4* bout = (float4*)(beta + (size_t)((bb*16 + t) * 8 + l) * 1024 + tid * 8);
        float4 v0 = e4[0], v1 = e4[1];
        bout[0] = make_float4(v0.x*w, v0.y*w, v0.z*w, v0.w*w);
        bout[1] = make_float4(v1.x*w, v1.y*w, v1.z*w, v1.w*w);
    }

    float a0=0.f, a1=0.f, a2=0.f, a3=0.f;
    for (int k0 = 0; k0 < 128; k0 += 32) {
        { int e = tid & 31, r = tid >> 5;
          #pragma unroll
          for (int i = 0; i < 4; i++) {
              int rr = r + i*4, g = m0 + rr, d = kb + k0 + e;
              float gir = g_gi2[g*768 + d]       + g_gi2[GI_PLANE + g*768 + d];
              float giz = g_gi2[g*768 + 256 + d] + g_gi2[GI_PLANE + g*768 + 256 + d];
              float gin = g_gi2[g*768 + 512 + d] + g_gi2[GI_PLANE + g*768 + 512 + d];
              float ghr = g_qtgh2[g*1024 + 256 + d] + g_qtgh2[QT_PLANE + g*1024 + 256 + d];
              float ghz = g_qtgh2[g*1024 + 512 + d] + g_qtgh2[QT_PLANE + g*1024 + 512 + d];
              float ghn = g_qtgh2[g*1024 + 768 + d] + g_qtgh2[QT_PLANE + g*1024 + 768 + d];
              float rg = sigm(gir + ghr);
              float z  = sigm(giz + ghz);
              float nn = tanhf(gin + rg * ghn);
              float s2 = (1.f - z) * nn + z * g_slots[g*256 + d];
              As[rr][e] = s2;
              if (blockIdx.x == 0) g_s2[g*256 + d] = s2;
          } }
        { int e = tid & 31, c = tid >> 5;
          #pragma unroll
          for (int i = 0; i < 8; i++) { int cc = c + i*4; Bs[e][cc] = W1[(size_t)(c0+cc)*256 + kb + k0 + e]; } }
        __syncthreads();
        #pragma unroll
        for (int e = 0; e < 32; e++) {
            float a = As[row][e];
            float4 b4 = *(const float4*)&Bs[e][cg*4];
            a0 = fmaf(a,b4.x,a0); a1 = fmaf(a,b4.y,a1); a2 = fmaf(a,b4.z,a2); a3 = fmaf(a,b4.w,a3);
        }
        __syncthreads();
    }
    int cb = c0 + cg*4;
    if (blockIdx.z == 0) { a0 += b1[cb]; a1 += b1[cb+1]; a2 += b1[cb+2]; a3 += b1[cb+3]; }
    *(float4*)&g_h1p[(size_t)blockIdx.z*H1_PLANE + (m0+row)*256 + cb] = make_float4(a0,a1,a2,a3);
}

// ffn2 + residual + LayerNorm.  grid 32 (4 rows each), 256 thr; 2 warps per row.
__global__ void ffn2_ln_kernel(const float* __restrict__ W2, const float* __restrict__ b2,
                               const float* __restrict__ lg, const float* __restrict__ lb,
                               float* __restrict__ outS, int t)
{
    __shared__ float As[4][256];
    __shared__ float Bs[256 * 33];
    __shared__ float rs[4][2], rq[4][2];
    const int tid = threadIdx.x;
    const int w = tid >> 5, lane = tid & 31;
    const int rr = w >> 1, h = w & 1;
    const int r0 = blockIdx.x * 4, row = r0 + rr;

    for (int i = tid; i < 1024; i += 256) {
        int rj = i >> 8, k = i & 255;
        float v = g_h1p[(r0 + rj)*256 + k] + g_h1p[H1_PLANE + (r0 + rj)*256 + k];
        As[rj][k] = fmaxf(v, 0.f);
    }
    float acc[4] = {0.f, 0.f, 0.f, 0.f};
    for (int e0 = 0; e0 < 256; e0 += 32) {
        __syncthreads();
        for (int idx = tid; idx < 8192; idx += 256) {
            int c = idx >> 5, e = idx & 31;
            Bs[c * 33 + e] = W2[(size_t)c * 256 + e0 + e];
        }
        __syncthreads();
        #pragma unroll
        for (int e = 0; e < 32; e++) {
            float a = As[rr][e0 + e];
            #pragma unroll
            for (int i = 0; i < 4; i++)
                acc[i] = fmaf(a, Bs[(h*128 + lane + 32*i) * 33 + e], acc[i]);
        }
    }
    float x[4], s = 0.f, q = 0.f;
    #pragma unroll
    for (int i = 0; i < 4; i++) {
        int c = h*128 + lane + 32*i;
        x[i] = acc[i] + b2[c] + g_s2[(size_t)row * 256 + c];
        s += x[i]; q += x[i] * x[i];
    }
    #pragma unroll
    for (int o = 16; o > 0; o >>= 1) {
        s += __shfl_xor_sync(0xffffffffu, s, o);
        q += __shfl_xor_sync(0xffffffffu, q, o);
    }
    if (lane == 0) { rs[rr][h] = s; rq[rr][h] = q; }
    __syncthreads();
    s = rs[rr][0] + rs[rr][1];
    q = rq[rr][0] + rq[rr][1];
    float mean = s * (1.f/256.f);
    float var  = q * (1.f/256.f) - mean * mean;
    float inv  = rsqrtf(var + 1e-5f);
    int b = row >> 3, l = row & 7;
    float* oS = outS + (size_t)((b*16 + t) * 8 + l) * 256;
    #pragma unroll
    for (int i = 0; i < 4; i++) {
        int c = h*128 + lane + 32*i;
        float y = (x[i] - mean) * inv * lg[c] + lb[c];
        g_slots[(size_t)row * 256 + c] = y;
        oS[c] = y;
    }
}

// ================= launcher =================
extern "C" void kernel_launch(void* const* d_in, const int* in_sizes, int n_in,
                              void* d_out, int out_size)
{
    const float* H    = (const float*)d_in[0];
    const float* eps  = (const float*)d_in[1];
    const float* mu   = (const float*)d_in[2];
    const float* ls   = (const float*)d_in[3];
    const float* Wq   = (const float*)d_in[4];
    const float* bq   = (const float*)d_in[5];
    const float* Wk   = (const float*)d_in[6];
    // d_in[7] = bk: row-constant in logits, cancels in softmax — provably unused.
    const float* Wv   = (const float*)d_in[8];
    const float* bv   = (const float*)d_in[9];
    const float* W_ih = (const float*)d_in[10];
    const float* b_ih = (const float*)d_in[11];
    const float* W_hh = (const float*)d_in[12];
    const float* b_hh = (const float*)d_in[13];
    const float* W1   = (const float*)d_in[14];
    const float* b1   = (const float*)d_in[15];
    const float* W2   = (const float*)d_in[16];
    const float* b2   = (const float*)d_in[17];
    const float* lng  = (const float*)d_in[18];
    const float* lnb  = (const float*)d_in[19];

    float* outS = (float*)d_out;
    float* outB = outS + S_ELEMS;

    // dynamic smem opt-in for the fused H-tile kernel (idempotent host call, not captured)
    const int SMEM_BYTES = (64*HPITCH + 2048 + 512 + 16 + 16 + 8) * 4;
    static int configured = 0;
    if (!configured) {
        cudaFuncSetAttribute(scoresU_kernel, cudaFuncAttributeMaxDynamicSharedMemorySize, SMEM_BYTES);
        configured = 1;
    }

    pre_misc<<<952, 256>>>(eps, mu, ls, W_hh, bq, Wk, b_hh, W_ih, bv, b_ih);
    pre_gemm<<<dim3(8, 32), 256>>>(Wq, Wk, W_ih, Wv);

    for (int t = 0; t < 16; t++) {
        k_qtgh<<<dim3(32, 8, 2), 128>>>();
        scoresU_kernel<<<dim3(16, 16), 256, SMEM_BYTES>>>(H, t);
        k_gi<<<dim3(24, 8, 2), 128>>>();
        ffn1_gru_kernel<<<dim3(8, 8, 2), 128>>>(W1, b1, outB, t);
        ffn2_ln_kernel<<<32, 256>>>(W2, b2, lng, lnb, outS, t);
    }
}

// round 11
// speedup vs baseline: 1.3295x; 1.3295x over previous
#include <cuda_runtime.h>
#include <math.h>

// B=16, K=16 steps, N=1024, D=256, L=8.  Rows = B*L = 128.
#define S_ELEMS (16*16*8*256)
#define QT_PLANE (128*1024)
#define GI_PLANE (128*768)
#define H1_PLANE (128*256)
#define UP_PLANE (128*256)
#define NB 128           // persistent blocks (< 148 SMs -> co-resident, barrier-safe)

// ---------------- scratch ----------------
__device__ __align__(16) float g_slots[128*256];
__device__ __align__(16) float g_Mcomb[256*1024];   // [k][0:256]=Wq^T Wk*scale, [k][256:1024]=W_hh^T
__device__ __align__(16) float g_cpart[8*1024];     // 8 e-partials of [scale*bq@Wk | b_hh]
__device__ __align__(16) float g_M2[768*256];       // W_ih @ Wv
__device__ __align__(16) float g_c2part[8*768];     // 8 e-partials of (W_ih@bv + b_ih)
__device__ __align__(16) float g_qtgh2[2*QT_PLANE]; // 2 K-split partials of [Qt | gh]
__device__ __align__(16) float g_escore[128*1024];  // exp(score - chunkmax)
__device__ __align__(16) float g_pmax[128*16];
__device__ __align__(16) float g_psum[128*16];
__device__ __align__(16) float g_upart[16*UP_PLANE];// UNnormalized expP@H partials per n-chunk
__device__ __align__(16) float g_U[128*256];        // flash-combined attn@H
__device__ __align__(16) float g_w[128*16];         // per-row per-chunk softmax weights
__device__ __align__(16) float g_gi2[2*GI_PLANE];   // 2 K-split partials of gi
__device__ __align__(16) float g_s2[128*256];
__device__ __align__(16) float g_h1p[4*H1_PLANE];   // 4 K-split partials of ffn1 pre-activation
__device__ unsigned g_barcnt;

__device__ __forceinline__ float sigm(float x) { return 1.f / (1.f + expf(-x)); }

// ============ 32x32-tile GEMM body (precompute only) ============
template<int AT>
__device__ __forceinline__ void gemm_body(
    int m0, int c0,
    const float* __restrict__ A, int lda,
    const float* __restrict__ B, int ldb,
    float* __restrict__ C, int ldc, float alpha)
{
    __shared__ float As[32][33];
    __shared__ __align__(16) float Bs[32][36];
    const int tid = threadIdx.x;
    const int row = tid & 31, cg = tid >> 5;
    float a0 = 0.f, a1 = 0.f, a2 = 0.f, a3 = 0.f;
    for (int k0 = 0; k0 < 256; k0 += 32) {
        if (AT) {
            int r = tid & 31, e = tid >> 5;
            #pragma unroll
            for (int i = 0; i < 4; i++) { int ee = e + i*8; As[r][ee] = A[(size_t)(k0+ee)*lda + m0 + r]; }
        } else {
            int e = tid & 31, r = tid >> 5;
            #pragma unroll
            for (int i = 0; i < 4; i++) { int rr = r + i*8; As[rr][e] = A[(size_t)(m0+rr)*lda + k0 + e]; }
        }
        {
            int c = tid & 31, e = tid >> 5;
            #pragma unroll
            for (int i = 0; i < 4; i++) { int ee = e + i*8; Bs[ee][c] = B[(size_t)(k0+ee)*ldb + c0 + c]; }
        }
        __syncthreads();
        #pragma unroll
        for (int e = 0; e < 32; e++) {
            float a = As[row][e];
            float4 b4 = *(const float4*)&Bs[e][cg*4];
            a0 = fmaf(a,b4.x,a0); a1 = fmaf(a,b4.y,a1); a2 = fmaf(a,b4.z,a2); a3 = fmaf(a,b4.w,a3);
        }
        __syncthreads();
    }
    int cb = c0 + cg*4;
    *(float4*)&C[(size_t)(m0+row)*ldc + cb] = make_float4(a0*alpha, a1*alpha, a2*alpha, a3*alpha);
}

// ================= precompute (2 kernels) =================
__global__ void pre_misc(const float* __restrict__ eps, const float* __restrict__ mu,
                         const float* __restrict__ ls, const float* __restrict__ W_hh,
                         const float* __restrict__ bq, const float* __restrict__ Wk,
                         const float* __restrict__ b_hh, const float* __restrict__ W_ih,
                         const float* __restrict__ bv, const float* __restrict__ b_ih)
{
    const int bx = blockIdx.x, tid = threadIdx.x;
    if (bx == 0 && tid == 0) g_barcnt = 0;          // reset megakernel barrier
    if (bx < 128) {
        int i = bx * 256 + tid;
        int ld = i & 2047;
        g_slots[i] = mu[ld] + expf(ls[ld]) * eps[i];
    } else if (bx < 896) {
        int idx = (bx - 128) * 256 + tid;           // 256x768
        int c = idx >> 8, k = idx & 255;
        g_Mcomb[k * 1024 + 256 + c] = W_hh[c * 256 + k];
    } else if (bx < 928) {
        int q = bx - 896;
        int p = q >> 2;
        int c = (q & 3) * 256 + tid;
        if (c < 256) {
            int e0 = p * 32;
            float s = 0.f;
            #pragma unroll 8
            for (int e = 0; e < 32; e++) s = fmaf(bq[e0+e], Wk[(e0+e)*256 + c], s);
            g_cpart[p * 1024 + c] = s * 0.0625f;
        } else {
            g_cpart[p * 1024 + c] = (p == 0) ? b_hh[c - 256] : 0.f;
        }
    } else {
        int q = bx - 928;
        int p = q / 3;
        int c = (q % 3) * 256 + tid;
        int e0 = p * 32;
        float s = (p == 0) ? b_ih[c] : 0.f;
        #pragma unroll 8
        for (int e = 0; e < 32; e++) s = fmaf(W_ih[c*256 + e0+e], bv[e0+e], s);
        g_c2part[p * 768 + c] = s;
    }
}

__global__ void pre_gemm(const float* __restrict__ Wq, const float* __restrict__ Wk,
                         const float* __restrict__ W_ih, const float* __restrict__ Wv)
{
    if (blockIdx.y < 8)
        gemm_body<1>(blockIdx.y*32, blockIdx.x*32, Wq,256, Wk,256, g_Mcomb,1024, 0.0625f);
    else
        gemm_body<0>((blockIdx.y-8)*32, blockIdx.x*32, W_ih,256, Wv,256, g_M2,256, 1.f);
}

// ================= persistent megakernel =================
__global__ void __launch_bounds__(512)
mega_kernel(const float* __restrict__ H,
            const float* __restrict__ W1, const float* __restrict__ b1,
            const float* __restrict__ W2, const float* __restrict__ b2,
            const float* __restrict__ lg, const float* __restrict__ lb,
            float* __restrict__ outS, float* __restrict__ outB)
{
    __shared__ __align__(16) float sm[10528];       // 42.1 KB, carved per phase
    const int bid = blockIdx.x, tid = threadIdx.x;
    unsigned nbar = 0;

    // device-wide barrier: release fence by all, arrive+spin by tid0, acquire fence
    auto gridbar = [&]() {
        __threadfence();                            // drain my stores to L2 (release)
        __syncthreads();                            // whole block's stores now global
        if (tid == 0) {
            atomicAdd(&g_barcnt, 1u);
            unsigned target = (nbar + 1) * NB;
            while (*(volatile unsigned*)&g_barcnt < target) __nanosleep(64);
            __threadfence();                        // acquire: CCTL.IVALL invalidates L1
        }
        nbar++;
        __syncthreads();
    };

    #pragma unroll 1
    for (int t = 0; t < 16; t++) {
        // ---------- Phase A: qtgh partials (512 tasks @128thr, 4 groups/block) ----------
        {
            const int g = tid >> 7, vt = tid & 127;
            int task = g * NB + bid;                 // 0..511
            int ks = task >> 8, rem = task & 255;
            int m0 = (rem >> 5) * 16, c0 = (rem & 31) * 32, kb = ks * 128;
            float* As = sm + g * 1680;               // [16][33]
            float* Bs = As + 528;                    // [32][36]
            const int row = vt & 15, cg = vt >> 4;
            float a0=0.f, a1=0.f, a2=0.f, a3=0.f;
            for (int k0 = 0; k0 < 128; k0 += 32) {
                { int e = vt & 31, r = vt >> 5;
                  #pragma unroll
                  for (int i = 0; i < 4; i++) {
                      int rr = r + i*4;
                      As[rr*33 + e] = __ldcg(&g_slots[(m0+rr)*256 + kb + k0 + e]);
                  } }
                { int c = vt & 31, e = vt >> 5;
                  #pragma unroll
                  for (int i = 0; i < 8; i++) {
                      int ee = e + i*4;
                      Bs[ee*36 + c] = g_Mcomb[(size_t)(kb+k0+ee)*1024 + c0 + c];
                  } }
                __syncthreads();
                #pragma unroll
                for (int e = 0; e < 32; e++) {
                    float a = As[row*33 + e];
                    float4 b4 = *(const float4*)&Bs[e*36 + cg*4];
                    a0 = fmaf(a,b4.x,a0); a1 = fmaf(a,b4.y,a1);
                    a2 = fmaf(a,b4.z,a2); a3 = fmaf(a,b4.w,a3);
                }
                __syncthreads();
            }
            int cb = c0 + cg*4;
            if (ks == 0) {
                #pragma unroll
                for (int p = 0; p < 8; p++) {
                    const float* bp = g_cpart + p * 1024;
                    a0 += bp[cb]; a1 += bp[cb+1]; a2 += bp[cb+2]; a3 += bp[cb+3];
                }
            }
            *(float4*)&g_qtgh2[(size_t)ks*QT_PLANE + (m0+row)*1024 + cb] = make_float4(a0,a1,a2,a3);
        }
        gridbar();

        // ---------- Phase B: scores + chunk stats + exp·H partials (256 tasks @256thr) ----------
        {
            const int g = tid >> 8, vt = tid & 255;
            int task = g * NB + bid;                 // 0..255
            int b = task >> 4, chunk = task & 15, n0 = chunk * 64;
            float* Qs    = sm + g * 2608;            // 2048
            float* attnS = Qs + 2048;                // 512
            float* redM  = attnS + 512;              // 16
            float* redS  = redM + 16;                // 16
            float* mrow  = redS + 16;                // 8
            const int nl = vt & 63, sg = vt >> 6, lane = vt & 31;

            for (int i = vt; i < 512; i += 256) {
                int s = i >> 6, d4 = i & 63;
                float4 x0 = __ldcg((const float4*)&g_qtgh2[(size_t)(b*8+s)*1024 + d4*4]);
                float4 x1 = __ldcg((const float4*)&g_qtgh2[QT_PLANE + (size_t)(b*8+s)*1024 + d4*4]);
                *(float4*)&Qs[s*256 + d4*4] = make_float4(x0.x+x1.x, x0.y+x1.y, x0.z+x1.z, x0.w+x1.w);
            }
            __syncthreads();

            // scores: per-thread row streaming from global (L1-reused across 4 sg-subsets)
            const float4* hrow = (const float4*)(H + ((size_t)(b*16 + t)*1024 + n0 + nl) * 256);
            float a0 = 0.f, a1 = 0.f;
            #pragma unroll 8
            for (int d4 = 0; d4 < 64; d4++) {
                float4 h4 = __ldg(&hrow[d4]);
                float4 q0 = *(const float4*)&Qs[(sg*2+0)*256 + d4*4];
                float4 q1 = *(const float4*)&Qs[(sg*2+1)*256 + d4*4];
                a0 = fmaf(h4.x,q0.x,a0); a0 = fmaf(h4.y,q0.y,a0);
                a0 = fmaf(h4.z,q0.z,a0); a0 = fmaf(h4.w,q0.w,a0);
                a1 = fmaf(h4.x,q1.x,a1); a1 = fmaf(h4.y,q1.y,a1);
                a1 = fmaf(h4.z,q1.z,a1); a1 = fmaf(h4.w,q1.w,a1);
            }
            #pragma unroll
            for (int i = 0; i < 2; i++) {
                float m = i ? a1 : a0;
                #pragma unroll
                for (int o = 16; o > 0; o >>= 1) m = fmaxf(m, __shfl_xor_sync(0xffffffffu, m, o));
                if (lane == 0) redM[(sg*2+i)*2 + (nl >> 5)] = m;
            }
            __syncthreads();
            if (vt < 8) {
                float m = fmaxf(redM[vt*2], redM[vt*2+1]);
                mrow[vt] = m;
                g_pmax[(b*8 + vt)*16 + chunk] = m;
            }
            __syncthreads();
            float e0v = expf(a0 - mrow[sg*2+0]);
            float e1v = expf(a1 - mrow[sg*2+1]);
            g_escore[(size_t)(b*8 + sg*2+0)*1024 + n0 + nl] = e0v;
            g_escore[(size_t)(b*8 + sg*2+1)*1024 + n0 + nl] = e1v;
            attnS[(sg*2+0)*64 + nl] = e0v;
            attnS[(sg*2+1)*64 + nl] = e1v;
            #pragma unroll
            for (int i = 0; i < 2; i++) {
                float e = i ? e1v : e0v;
                #pragma unroll
                for (int o = 16; o > 0; o >>= 1) e += __shfl_xor_sync(0xffffffffu, e, o);
                if (lane == 0) redS[(sg*2+i)*2 + (nl >> 5)] = e;
            }
            __syncthreads();
            if (vt < 8) g_psum[(b*8 + vt)*16 + chunk] = redS[vt*2] + redS[vt*2+1];

            // exp·H partials: column streaming (L1-hot from scores pass)
            const float* hb = H + ((size_t)(b*16 + t)*1024 + n0) * 256;
            float acc[8] = {0.f,0.f,0.f,0.f,0.f,0.f,0.f,0.f};
            #pragma unroll 8
            for (int n = 0; n < 64; n++) {
                float hv = __ldg(&hb[(size_t)n*256 + vt]);
                #pragma unroll
                for (int s = 0; s < 8; s++) acc[s] = fmaf(attnS[s*64 + n], hv, acc[s]);
            }
            float* up = g_upart + (size_t)chunk * UP_PLANE;
            #pragma unroll
            for (int s = 0; s < 8; s++) up[(b*8 + s)*256 + vt] = acc[s];
        }
        gridbar();

        // ---------- Phase B2: flash combine U + attn weights (128 tasks = 1 row/block) ----------
        {
            int r = bid;
            float* pm   = sm;        // 16
            float* ps   = sm + 16;   // 16
            float* ws   = sm + 32;   // 16
            float* mS   = sm + 48;   // 2
            float* comb = sm + 64;   // 256
            if (tid < 16) {
                pm[tid] = __ldcg(&g_pmax[r*16 + tid]);
                ps[tid] = __ldcg(&g_psum[r*16 + tid]);
            }
            __syncthreads();
            if (tid == 0) {
                float m = pm[0];
                #pragma unroll
                for (int c = 1; c < 16; c++) m = fmaxf(m, pm[c]);
                float S = 0.f;
                #pragma unroll
                for (int c = 0; c < 16; c++) S += ps[c] * expf(pm[c] - m);
                mS[0] = m; mS[1] = 1.f / S;
            }
            __syncthreads();
            if (tid < 16) {
                float w = expf(pm[tid] - mS[0]) * mS[1];
                ws[tid] = w;
                g_w[r*16 + tid] = w;
            }
            __syncthreads();
            int j = tid & 255, half = tid >> 8;
            float part = 0.f;
            #pragma unroll
            for (int p = 0; p < 8; p++) {
                int c = half*8 + p;
                part = fmaf(ws[c], __ldcg(&g_upart[(size_t)c*UP_PLANE + r*256 + j]), part);
            }
            if (half == 0) comb[j] = part;
            __syncthreads();
            if (half == 1) g_U[r*256 + j] = part + comb[j];
        }
        gridbar();

        // ---------- Phase C: gi partials = U @ M2^T (+c2)  (384 tasks @128thr) ----------
        {
            const int g = tid >> 7, vt = tid & 127;
            int task = g * NB + bid;                 // 0..511, valid < 384
            bool act = task < 384;
            int tk = act ? task : 0;
            int colT = tk % 24, rowT = (tk / 24) & 7, ks = tk / 192;
            int m0 = rowT*16, c0 = colT*32, kb = ks*128;
            float* As = sm + g * 1680;
            float* Bs = As + 528;
            const int row = vt & 15, cg = vt >> 4;
            float a0=0.f, a1=0.f, a2=0.f, a3=0.f;
            for (int k0 = 0; k0 < 128; k0 += 32) {
                { int e = vt & 31, r = vt >> 5;
                  #pragma unroll
                  for (int i = 0; i < 4; i++) {
                      int rr = r + i*4;
                      As[rr*33 + e] = __ldcg(&g_U[(m0+rr)*256 + kb + k0 + e]);
                  } }
                { int e = vt & 31, c = vt >> 5;
                  #pragma unroll
                  for (int i = 0; i < 8; i++) {
                      int cc = c + i*4;
                      Bs[e*36 + cc] = g_M2[(size_t)(c0+cc)*256 + kb + k0 + e];
                  } }
                __syncthreads();
                #pragma unroll
                for (int e = 0; e < 32; e++) {
                    float a = As[row*33 + e];
                    float4 b4 = *(const float4*)&Bs[e*36 + cg*4];
                    a0 = fmaf(a,b4.x,a0); a1 = fmaf(a,b4.y,a1);
                    a2 = fmaf(a,b4.z,a2); a3 = fmaf(a,b4.w,a3);
                }
                __syncthreads();
            }
            int cb = c0 + cg*4;
            if (ks == 0) {
                #pragma unroll
                for (int p = 0; p < 8; p++) {
                    const float* bp = g_c2part + p * 768;
                    a0 += bp[cb]; a1 += bp[cb+1]; a2 += bp[cb+2]; a3 += bp[cb+3];
                }
            }
            if (act)
                *(float4*)&g_gi2[(size_t)ks*GI_PLANE + (m0+row)*768 + cb] = make_float4(a0,a1,a2,a3);
        }
        gridbar();

        // ---------- Phase D: GRU + ffn1 partials + Beta writer (256 tasks @128thr) ----------
        {
            const int g = tid >> 7, vt = tid & 127;
            int task = g * NB + bid;                 // 0..511, valid < 256
            bool act = task < 256;
            int tk = act ? task : 0;
            int ks = tk >> 6, rowT = (tk >> 3) & 7, colT = tk & 7;
            int m0 = rowT*16, c0 = colT*32, kb = ks*64;

            if (task < 128) {                        // Beta writer: row r = task
                int r = task;
                float w = __ldcg(&g_w[r*16 + (vt >> 3)]);
                const float4* e4 = (const float4*)(g_escore + (size_t)r*1024 + vt*8);
                float4 v0 = __ldcg(e4), v1 = __ldcg(e4 + 1);
                int bb = r >> 3, l = r & 7;
                float4* bo = (float4*)(outB + (size_t)((bb*16 + t)*8 + l)*1024 + vt*8);
                bo[0] = make_float4(v0.x*w, v0.y*w, v0.z*w, v0.w*w);
                bo[1] = make_float4(v1.x*w, v1.y*w, v1.z*w, v1.w*w);
            }

            float* As = sm + g * 1680;
            float* Bs = As + 528;
            const int row = vt & 15, cg = vt >> 4;
            float a0=0.f, a1=0.f, a2=0.f, a3=0.f;
            for (int k0 = 0; k0 < 64; k0 += 32) {
                { int e = vt & 31, r = vt >> 5;
                  #pragma unroll
                  for (int i = 0; i < 4; i++) {
                      int rr = r + i*4, gr = m0 + rr, d = kb + k0 + e;
                      float gir = __ldcg(&g_gi2[gr*768 + d])       + __ldcg(&g_gi2[GI_PLANE + gr*768 + d]);
                      float giz = __ldcg(&g_gi2[gr*768 + 256 + d]) + __ldcg(&g_gi2[GI_PLANE + gr*768 + 256 + d]);
                      float gin = __ldcg(&g_gi2[gr*768 + 512 + d]) + __ldcg(&g_gi2[GI_PLANE + gr*768 + 512 + d]);
                      float ghr = __ldcg(&g_qtgh2[gr*1024 + 256 + d]) + __ldcg(&g_qtgh2[QT_PLANE + gr*1024 + 256 + d]);
                      float ghz = __ldcg(&g_qtgh2[gr*1024 + 512 + d]) + __ldcg(&g_qtgh2[QT_PLANE + gr*1024 + 512 + d]);
                      float ghn = __ldcg(&g_qtgh2[gr*1024 + 768 + d]) + __ldcg(&g_qtgh2[QT_PLANE + gr*1024 + 768 + d]);
                      float rg = sigm(gir + ghr);
                      float z  = sigm(giz + ghz);
                      float nn = tanhf(gin + rg * ghn);
                      float s2 = (1.f - z) * nn + z * __ldcg(&g_slots[gr*256 + d]);
                      As[rr*33 + e] = s2;
                      if (act && colT == 0) g_s2[gr*256 + d] = s2;
                  } }
                { int e = vt & 31, c = vt >> 5;
                  #pragma unroll
                  for (int i = 0; i < 8; i++) {
                      int cc = c + i*4;
                      Bs[e*36 + cc] = W1[(size_t)(c0+cc)*256 + kb + k0 + e];
                  } }
                __syncthreads();
                #pragma unroll
                for (int e = 0; e < 32; e++) {
                    float a = As[row*33 + e];
                    float4 b4 = *(const float4*)&Bs[e*36 + cg*4];
                    a0 = fmaf(a,b4.x,a0); a1 = fmaf(a,b4.y,a1);
                    a2 = fmaf(a,b4.z,a2); a3 = fmaf(a,b4.w,a3);
                }
                __syncthreads();
            }
            int cb = c0 + cg*4;
            if (ks == 0) { a0 += b1[cb]; a1 += b1[cb+1]; a2 += b1[cb+2]; a3 += b1[cb+3]; }
            if (act)
                *(float4*)&g_h1p[(size_t)ks*H1_PLANE + (m0+row)*256 + cb] = make_float4(a0,a1,a2,a3);
        }
        gridbar();

        // ---------- Phase E: ffn2 + residual + LN (16 tasks @512thr: 8 rows/block) ----------
        {
            bool act = bid < 16;
            int r0 = (act ? bid : 0) * 8;
            float* Bs = sm;            // 256*33 = 8448
            float* As = sm + 8448;     // 8*256  = 2048
            float* rs = sm + 10496;    // 16
            float* rq = sm + 10512;    // 16
            const int w = tid >> 5, lane = tid & 31;
            const int rr = w >> 1, h = w & 1;
            const int rowr = r0 + rr;

            for (int i = tid; i < 2048; i += 512) {
                int rj = i >> 8, k = i & 255;
                size_t off = (size_t)(r0 + rj)*256 + k;
                float v = __ldcg(&g_h1p[off]) + __ldcg(&g_h1p[H1_PLANE + off])
                        + __ldcg(&g_h1p[2*H1_PLANE + off]) + __ldcg(&g_h1p[3*H1_PLANE + off]);
                As[rj*256 + k] = fmaxf(v, 0.f);
            }
            float acc[4] = {0.f, 0.f, 0.f, 0.f};
            for (int e0 = 0; e0 < 256; e0 += 32) {
                __syncthreads();
                for (int idx = tid; idx < 8192; idx += 512) {
                    int c = idx >> 5, e = idx & 31;
                    Bs[c*33 + e] = W2[(size_t)c*256 + e0 + e];
                }
                __syncthreads();
                #pragma unroll
                for (int e = 0; e < 32; e++) {
                    float a = As[rr*256 + e0 + e];
                    #pragma unroll
                    for (int i = 0; i < 4; i++)
                        acc[i] = fmaf(a, Bs[(h*128 + lane + 32*i)*33 + e], acc[i]);
                }
            }
            float x[4], s = 0.f, q = 0.f;
            #pragma unroll
            for (int i = 0; i < 4; i++) {
                int c = h*128 + lane + 32*i;
                x[i] = acc[i] + b2[c] + __ldcg(&g_s2[(size_t)rowr*256 + c]);
                s += x[i]; q += x[i]*x[i];
            }
            #pragma unroll
            for (int o = 16; o > 0; o >>= 1) {
                s += __shfl_xor_sync(0xffffffffu, s, o);
                q += __shfl_xor_sync(0xffffffffu, q, o);
            }
            __syncthreads();
            if (lane == 0) { rs[rr*2 + h] = s; rq[rr*2 + h] = q; }
            __syncthreads();
            s = rs[rr*2] + rs[rr*2+1];
            q = rq[rr*2] + rq[rr*2+1];
            float mean = s * (1.f/256.f);
            float var  = q * (1.f/256.f) - mean*mean;
            float inv  = rsqrtf(var + 1e-5f);
            if (act) {
                int bb = rowr >> 3, l = rowr & 7;
                float* oS = outS + (size_t)((bb*16 + t)*8 + l)*256;
                #pragma unroll
                for (int i = 0; i < 4; i++) {
                    int c = h*128 + lane + 32*i;
                    float y = (x[i] - mean) * inv * lg[c] + lb[c];
                    g_slots[(size_t)rowr*256 + c] = y;
                    oS[c] = y;
                }
            }
        }
        gridbar();
    }
}

// ================= launcher =================
extern "C" void kernel_launch(void* const* d_in, const int* in_sizes, int n_in,
                              void* d_out, int out_size)
{
    const float* H    = (const float*)d_in[0];
    const float* eps  = (const float*)d_in[1];
    const float* mu   = (const float*)d_in[2];
    const float* ls   = (const float*)d_in[3];
    const float* Wq   = (const float*)d_in[4];
    const float* bq   = (const float*)d_in[5];
    const float* Wk   = (const float*)d_in[6];
    // d_in[7] = bk: row-constant in logits, cancels in softmax — provably unused.
    const float* Wv   = (const float*)d_in[8];
    const float* bv   = (const float*)d_in[9];
    const float* W_ih = (const float*)d_in[10];
    const float* b_ih = (const float*)d_in[11];
    const float* W_hh = (const float*)d_in[12];
    const float* b_hh = (const float*)d_in[13];
    const float* W1   = (const float*)d_in[14];
    const float* b1   = (const float*)d_in[15];
    const float* W2   = (const float*)d_in[16];
    const float* b2   = (const float*)d_in[17];
    const float* lng  = (const float*)d_in[18];
    const float* lnb  = (const float*)d_in[19];

    float* outS = (float*)d_out;
    float* outB = outS + S_ELEMS;

    pre_misc<<<952, 256>>>(eps, mu, ls, W_hh, bq, Wk, b_hh, W_ih, bv, b_ih);
    pre_gemm<<<dim3(8, 32), 256>>>(Wq, Wk, W_ih, Wv);
    mega_kernel<<<NB, 512>>>(H, W1, b1, W2, b2, lng, lnb, outS, outB);
}

// round 12
// speedup vs baseline: 1.5381x; 1.1569x over previous
#include <cuda_runtime.h>
#include <math.h>

// B=16, K=16 steps, N=1024, D=256, L=8.  Rows = B*L = 128.  8 n-chunks of 128.
#define S_ELEMS (16*16*8*256)
#define QT_PLANE (128*1024)
#define GI_PLANE (128*768)
#define H1_PLANE (128*256)
#define UP_PLANE (128*256)
#define NB 128           // persistent blocks (< 148 SMs -> co-resident, barrier-safe)

// ---------------- scratch ----------------
__device__ __align__(16) float g_slots[128*256];
__device__ __align__(16) float g_Mcomb[256*1024];   // [k][0:256]=Wq^T Wk*scale, [k][256:1024]=W_hh^T
__device__ __align__(16) float g_cpart[8*1024];     // 8 e-partials of [scale*bq@Wk | b_hh]
__device__ __align__(16) float g_M2[768*256];       // W_ih @ Wv
__device__ __align__(16) float g_c2part[8*768];     // 8 e-partials of (W_ih@bv + b_ih)
__device__ __align__(16) float g_qtgh2[2*QT_PLANE]; // 2 K-split partials of [Qt | gh]
__device__ __align__(16) float g_escore[128*1024];  // exp(score - chunkmax)
__device__ __align__(16) float g_pmax[128*8];
__device__ __align__(16) float g_psum[128*8];
__device__ __align__(16) float g_upart[8*UP_PLANE]; // UNnormalized expP@H partials per n-chunk
__device__ __align__(16) float g_gi2[2*GI_PLANE];   // 2 K-split partials of gi
__device__ __align__(16) float g_s2[128*256];
__device__ __align__(16) float g_h1p[8*H1_PLANE];   // 8 K-split partials of ffn1 pre-activation
__device__ unsigned g_barcnt;

__device__ __forceinline__ float sigm(float x) { return 1.f / (1.f + expf(-x)); }

// ============ 32x32-tile GEMM body (precompute only) ============
template<int AT>
__device__ __forceinline__ void gemm_body(
    int m0, int c0,
    const float* __restrict__ A, int lda,
    const float* __restrict__ B, int ldb,
    float* __restrict__ C, int ldc, float alpha)
{
    __shared__ float As[32][33];
    __shared__ __align__(16) float Bs[32][36];
    const int tid = threadIdx.x;
    const int row = tid & 31, cg = tid >> 5;
    float a0 = 0.f, a1 = 0.f, a2 = 0.f, a3 = 0.f;
    for (int k0 = 0; k0 < 256; k0 += 32) {
        if (AT) {
            int r = tid & 31, e = tid >> 5;
            #pragma unroll
            for (int i = 0; i < 4; i++) { int ee = e + i*8; As[r][ee] = A[(size_t)(k0+ee)*lda + m0 + r]; }
        } else {
            int e = tid & 31, r = tid >> 5;
            #pragma unroll
            for (int i = 0; i < 4; i++) { int rr = r + i*8; As[rr][e] = A[(size_t)(m0+rr)*lda + k0 + e]; }
        }
        {
            int c = tid & 31, e = tid >> 5;
            #pragma unroll
            for (int i = 0; i < 4; i++) { int ee = e + i*8; Bs[ee][c] = B[(size_t)(k0+ee)*ldb + c0 + c]; }
        }
        __syncthreads();
        #pragma unroll
        for (int e = 0; e < 32; e++) {
            float a = As[row][e];
            float4 b4 = *(const float4*)&Bs[e][cg*4];
            a0 = fmaf(a,b4.x,a0); a1 = fmaf(a,b4.y,a1); a2 = fmaf(a,b4.z,a2); a3 = fmaf(a,b4.w,a3);
        }
        __syncthreads();
    }
    int cb = c0 + cg*4;
    *(float4*)&C[(size_t)(m0+row)*ldc + cb] = make_float4(a0*alpha, a1*alpha, a2*alpha, a3*alpha);
}

// ================= precompute (2 kernels) =================
__global__ void pre_misc(const float* __restrict__ eps, const float* __restrict__ mu,
                         const float* __restrict__ ls, const float* __restrict__ W_hh,
                         const float* __restrict__ bq, const float* __restrict__ Wk,
                         const float* __restrict__ b_hh, const float* __restrict__ W_ih,
                         const float* __restrict__ bv, const float* __restrict__ b_ih)
{
    const int bx = blockIdx.x, tid = threadIdx.x;
    if (bx == 0 && tid == 0) g_barcnt = 0;          // reset megakernel barrier
    if (bx < 128) {
        int i = bx * 256 + tid;
        int ld = i & 2047;
        g_slots[i] = mu[ld] + expf(ls[ld]) * eps[i];
    } else if (bx < 896) {
        int idx = (bx - 128) * 256 + tid;           // 256x768
        int c = idx >> 8, k = idx & 255;
        g_Mcomb[k * 1024 + 256 + c] = W_hh[c * 256 + k];
    } else if (bx < 928) {
        int q = bx - 896;
        int p = q >> 2;
        int c = (q & 3) * 256 + tid;
        if (c < 256) {
            int e0 = p * 32;
            float s = 0.f;
            #pragma unroll 8
            for (int e = 0; e < 32; e++) s = fmaf(bq[e0+e], Wk[(e0+e)*256 + c], s);
            g_cpart[p * 1024 + c] = s * 0.0625f;
        } else {
            g_cpart[p * 1024 + c] = (p == 0) ? b_hh[c - 256] : 0.f;
        }
    } else {
        int q = bx - 928;
        int p = q / 3;
        int c = (q % 3) * 256 + tid;
        int e0 = p * 32;
        float s = (p == 0) ? b_ih[c] : 0.f;
        #pragma unroll 8
        for (int e = 0; e < 32; e++) s = fmaf(W_ih[c*256 + e0+e], bv[e0+e], s);
        g_c2part[p * 768 + c] = s;
    }
}

__global__ void pre_gemm(const float* __restrict__ Wq, const float* __restrict__ Wk,
                         const float* __restrict__ W_ih, const float* __restrict__ Wv)
{
    if (blockIdx.y < 8)
        gemm_body<1>(blockIdx.y*32, blockIdx.x*32, Wq,256, Wk,256, g_Mcomb,1024, 0.0625f);
    else
        gemm_body<0>((blockIdx.y-8)*32, blockIdx.x*32, W_ih,256, Wv,256, g_M2,256, 1.f);
}

// ================= persistent megakernel =================
__global__ void __launch_bounds__(512)
mega_kernel(const float* __restrict__ H,
            const float* __restrict__ W1, const float* __restrict__ b1,
            const float* __restrict__ W2, const float* __restrict__ b2,
            const float* __restrict__ lg, const float* __restrict__ lb,
            float* __restrict__ outS, float* __restrict__ outB)
{
    __shared__ __align__(16) float sm[10528];       // 42.1 KB, carved per phase
    const int bid = blockIdx.x, tid = threadIdx.x;
    unsigned nbar = 0;

    auto gridbar = [&]() {
        __threadfence();
        __syncthreads();
        if (tid == 0) {
            atomicAdd(&g_barcnt, 1u);
            unsigned target = (nbar + 1) * NB;
            while (*(volatile unsigned*)&g_barcnt < target) { }
            __threadfence();
        }
        nbar++;
        __syncthreads();
    };

    #pragma unroll 1
    for (int t = 0; t < 16; t++) {
        // ---------- Phase A: qtgh partials (512 tasks @128thr, 4 groups/block) ----------
        {
            const int g = tid >> 7, vt = tid & 127;
            int task = g * NB + bid;                 // 0..511
            int ks = task >> 8, rem = task & 255;
            int m0 = (rem >> 5) * 16, c0 = (rem & 31) * 32, kb = ks * 128;
            float* As = sm + g * 1680;               // [16][33]
            float* Bs = As + 528;                    // [32][36]
            const int row = vt & 15, cg = vt >> 4;
            float a0=0.f, a1=0.f, a2=0.f, a3=0.f;
            for (int k0 = 0; k0 < 128; k0 += 32) {
                { int e = vt & 31, r = vt >> 5;
                  #pragma unroll
                  for (int i = 0; i < 4; i++) {
                      int rr = r + i*4;
                      As[rr*33 + e] = __ldcg(&g_slots[(m0+rr)*256 + kb + k0 + e]);
                  } }
                { int c = vt & 31, e = vt >> 5;
                  #pragma unroll
                  for (int i = 0; i < 8; i++) {
                      int ee = e + i*4;
                      Bs[ee*36 + c] = g_Mcomb[(size_t)(kb+k0+ee)*1024 + c0 + c];
                  } }
                __syncthreads();
                #pragma unroll
                for (int e = 0; e < 32; e++) {
                    float a = As[row*33 + e];
                    float4 b4 = *(const float4*)&Bs[e*36 + cg*4];
                    a0 = fmaf(a,b4.x,a0); a1 = fmaf(a,b4.y,a1);
                    a2 = fmaf(a,b4.z,a2); a3 = fmaf(a,b4.w,a3);
                }
                __syncthreads();
            }
            int cb = c0 + cg*4;
            if (ks == 0) {
                #pragma unroll
                for (int p = 0; p < 8; p++) {
                    const float* bp = g_cpart + p * 1024;
                    a0 += bp[cb]; a1 += bp[cb+1]; a2 += bp[cb+2]; a3 += bp[cb+3];
                }
            }
            *(float4*)&g_qtgh2[(size_t)ks*QT_PLANE + (m0+row)*1024 + cb] = make_float4(a0,a1,a2,a3);
        }
        gridbar();

        // ---------- Phase B: scores + chunk stats + exp·H partials (128 tasks @512thr, 1/block) ----------
        {
            const int b = bid >> 3, chunk = bid & 7, n0 = chunk * 128;
            float* Qs    = sm;                       // 2048
            float* attnS = sm + 2048;                // 1024
            float* redM  = sm + 3072;                // 32
            float* redS  = sm + 3104;                // 32
            float* mrow  = sm + 3136;                // 8
            const int nl = tid & 127, sg = tid >> 7, lane = tid & 31, w = tid >> 5;

            {   // Q = sum of 2 qtgh k-partials (one float4 per thread)
                int s = tid >> 6, d4 = tid & 63;
                float4 x0 = __ldcg((const float4*)&g_qtgh2[(size_t)(b*8+s)*1024 + d4*4]);
                float4 x1 = __ldcg((const float4*)&g_qtgh2[QT_PLANE + (size_t)(b*8+s)*1024 + d4*4]);
                *(float4*)&Qs[s*256 + d4*4] = make_float4(x0.x+x1.x, x0.y+x1.y, x0.z+x1.z, x0.w+x1.w);
            }
            __syncthreads();

            // scores: thread owns row nl for 2 slots (4x sg redundancy -> L1)
            const float4* hrow = (const float4*)(H + ((size_t)(b*16 + t)*1024 + n0 + nl) * 256);
            float a0 = 0.f, a1 = 0.f;
            #pragma unroll 8
            for (int d4 = 0; d4 < 64; d4++) {
                float4 h4 = __ldg(&hrow[d4]);
                float4 q0 = *(const float4*)&Qs[(sg*2+0)*256 + d4*4];
                float4 q1 = *(const float4*)&Qs[(sg*2+1)*256 + d4*4];
                a0 = fmaf(h4.x,q0.x,a0); a0 = fmaf(h4.y,q0.y,a0);
                a0 = fmaf(h4.z,q0.z,a0); a0 = fmaf(h4.w,q0.w,a0);
                a1 = fmaf(h4.x,q1.x,a1); a1 = fmaf(h4.y,q1.y,a1);
                a1 = fmaf(h4.z,q1.z,a1); a1 = fmaf(h4.w,q1.w,a1);
            }
            #pragma unroll
            for (int i = 0; i < 2; i++) {
                float m = i ? a1 : a0;
                #pragma unroll
                for (int o = 16; o > 0; o >>= 1) m = fmaxf(m, __shfl_xor_sync(0xffffffffu, m, o));
                if (lane == 0) redM[(sg*2+i)*4 + (w & 3)] = m;
            }
            __syncthreads();
            if (tid < 8) {
                float m = fmaxf(fmaxf(redM[tid*4], redM[tid*4+1]), fmaxf(redM[tid*4+2], redM[tid*4+3]));
                mrow[tid] = m;
                g_pmax[(b*8 + tid)*8 + chunk] = m;
            }
            __syncthreads();
            float e0v = expf(a0 - mrow[sg*2+0]);
            float e1v = expf(a1 - mrow[sg*2+1]);
            g_escore[(size_t)(b*8 + sg*2+0)*1024 + n0 + nl] = e0v;
            g_escore[(size_t)(b*8 + sg*2+1)*1024 + n0 + nl] = e1v;
            attnS[(sg*2+0)*128 + nl] = e0v;
            attnS[(sg*2+1)*128 + nl] = e1v;
            #pragma unroll
            for (int i = 0; i < 2; i++) {
                float e = i ? e1v : e0v;
                #pragma unroll
                for (int o = 16; o > 0; o >>= 1) e += __shfl_xor_sync(0xffffffffu, e, o);
                if (lane == 0) redS[(sg*2+i)*4 + (w & 3)] = e;
            }
            __syncthreads();
            if (tid < 8)
                g_psum[(b*8 + tid)*8 + chunk] = redS[tid*4] + redS[tid*4+1] + redS[tid*4+2] + redS[tid*4+3];

            // exp·H partials: thread owns column j for 4 slots (2x redundancy -> L1-hot)
            const int j = tid & 255, sh = tid >> 8;
            const float* hb = H + ((size_t)(b*16 + t)*1024 + n0) * 256;
            float acc[4] = {0.f,0.f,0.f,0.f};
            #pragma unroll 8
            for (int n = 0; n < 128; n++) {
                float hv = __ldg(&hb[(size_t)n*256 + j]);
                #pragma unroll
                for (int s = 0; s < 4; s++) acc[s] = fmaf(attnS[(sh*4+s)*128 + n], hv, acc[s]);
            }
            float* up = g_upart + (size_t)chunk * UP_PLANE;
            #pragma unroll
            for (int s = 0; s < 4; s++) up[(b*8 + sh*4 + s)*256 + j] = acc[s];
        }
        gridbar();

        // ---------- Phase C: gi partials = (flash-combined U) @ M2^T (+c2)  (384 tasks @128thr) ----------
        {
            const int g = tid >> 7, vt = tid & 127;
            int task = g * NB + bid;                 // 0..511, valid < 384
            bool act = task < 384;
            int tk = act ? task : 0;
            int colT = tk % 24, rowT = (tk / 24) & 7, ks = tk / 192;
            int m0 = rowT*16, c0 = colT*32, kb = ks*128;
            float* As = sm + g * 1824;
            float* Bs = As + 528;
            float* ws = Bs + 1152;                   // [16][9]
            const int row = vt & 15, cg = vt >> 4;

            if (vt < 16) {
                int r = m0 + vt;
                float pm[8];
                #pragma unroll
                for (int c = 0; c < 8; c++) pm[c] = __ldcg(&g_pmax[r*8 + c]);
                float m = pm[0];
                #pragma unroll
                for (int c = 1; c < 8; c++) m = fmaxf(m, pm[c]);
                float S = 0.f;
                #pragma unroll
                for (int c = 0; c < 8; c++) S += __ldcg(&g_psum[r*8 + c]) * expf(pm[c] - m);
                float invS = 1.f / S;
                #pragma unroll
                for (int c = 0; c < 8; c++) ws[vt*9 + c] = expf(pm[c] - m) * invS;
            }
            __syncthreads();

            float a0=0.f, a1=0.f, a2=0.f, a3=0.f;
            for (int k0 = 0; k0 < 128; k0 += 32) {
                { int e = vt & 31, r = vt >> 5;
                  #pragma unroll
                  for (int i = 0; i < 4; i++) {
                      int rr = r + i*4;
                      size_t idx = (size_t)(m0+rr)*256 + kb + k0 + e;
                      float v = 0.f;
                      #pragma unroll
                      for (int p = 0; p < 8; p++)
                          v = fmaf(__ldcg(&g_upart[(size_t)p*UP_PLANE + idx]), ws[rr*9 + p], v);
                      As[rr*33 + e] = v;
                  } }
                { int e = vt & 31, c = vt >> 5;
                  #pragma unroll
                  for (int i = 0; i < 8; i++) {
                      int cc = c + i*4;
                      Bs[e*36 + cc] = g_M2[(size_t)(c0+cc)*256 + kb + k0 + e];
                  } }
                __syncthreads();
                #pragma unroll
                for (int e = 0; e < 32; e++) {
                    float a = As[row*33 + e];
                    float4 b4 = *(const float4*)&Bs[e*36 + cg*4];
                    a0 = fmaf(a,b4.x,a0); a1 = fmaf(a,b4.y,a1);
                    a2 = fmaf(a,b4.z,a2); a3 = fmaf(a,b4.w,a3);
                }
                __syncthreads();
            }
            int cb = c0 + cg*4;
            if (ks == 0) {
                #pragma unroll
                for (int p = 0; p < 8; p++) {
                    const float* bp = g_c2part + p * 768;
                    a0 += bp[cb]; a1 += bp[cb+1]; a2 += bp[cb+2]; a3 += bp[cb+3];
                }
            }
            if (act)
                *(float4*)&g_gi2[(size_t)ks*GI_PLANE + (m0+row)*768 + cb] = make_float4(a0,a1,a2,a3);
        }
        gridbar();

        // ---------- Phase D: GRU + ffn1 partials + Beta writer (512 tasks @128thr, 100% fill) ----------
        {
            const int g = tid >> 7, vt = tid & 127;
            int task = g * NB + bid;                 // 0..511
            int ks = task >> 6, rowT = (task >> 3) & 7, colT = task & 7;
            int m0 = rowT*16, c0 = colT*32, kb = ks*32;

            if (task < 128) {                        // Beta writer: row r = task
                int r = task;
                float pm[8];
                #pragma unroll
                for (int c = 0; c < 8; c++) pm[c] = __ldcg(&g_pmax[r*8 + c]);
                float m = pm[0];
                #pragma unroll
                for (int c = 1; c < 8; c++) m = fmaxf(m, pm[c]);
                float S = 0.f;
                #pragma unroll
                for (int c = 0; c < 8; c++) S += __ldcg(&g_psum[r*8 + c]) * expf(pm[c] - m);
                int cch = vt >> 4;
                float wv = expf(pm[cch] - m) / S;
                int base = cch*128 + (vt & 15)*8;
                const float4* e4 = (const float4*)(g_escore + (size_t)r*1024 + base);
                float4 v0 = __ldcg(e4), v1 = __ldcg(e4 + 1);
                int bb = r >> 3, l = r & 7;
                float4* bo = (float4*)(outB + (size_t)((bb*16 + t)*8 + l)*1024 + base);
                bo[0] = make_float4(v0.x*wv, v0.y*wv, v0.z*wv, v0.w*wv);
                bo[1] = make_float4(v1.x*wv, v1.y*wv, v1.z*wv, v1.w*wv);
            }

            float* As = sm + g * 1680;
            float* Bs = As + 528;
            const int row = vt & 15, cg = vt >> 4;
            float a0=0.f, a1=0.f, a2=0.f, a3=0.f;
            {   // single 32-wide k chunk: kb..kb+31
                { int e = vt & 31, r = vt >> 5;
                  #pragma unroll
                  for (int i = 0; i < 4; i++) {
                      int rr = r + i*4, gr = m0 + rr, d = kb + e;
                      float gir = __ldcg(&g_gi2[gr*768 + d])       + __ldcg(&g_gi2[GI_PLANE + gr*768 + d]);
                      float giz = __ldcg(&g_gi2[gr*768 + 256 + d]) + __ldcg(&g_gi2[GI_PLANE + gr*768 + 256 + d]);
                      float gin = __ldcg(&g_gi2[gr*768 + 512 + d]) + __ldcg(&g_gi2[GI_PLANE + gr*768 + 512 + d]);
                      float ghr = __ldcg(&g_qtgh2[gr*1024 + 256 + d]) + __ldcg(&g_qtgh2[QT_PLANE + gr*1024 + 256 + d]);
                      float ghz = __ldcg(&g_qtgh2[gr*1024 + 512 + d]) + __ldcg(&g_qtgh2[QT_PLANE + gr*1024 + 512 + d]);
                      float ghn = __ldcg(&g_qtgh2[gr*1024 + 768 + d]) + __ldcg(&g_qtgh2[QT_PLANE + gr*1024 + 768 + d]);
                      float rg = sigm(gir + ghr);
                      float z  = sigm(giz + ghz);
                      float nn = tanhf(gin + rg * ghn);
                      float s2 = (1.f - z) * nn + z * __ldcg(&g_slots[gr*256 + d]);
                      As[rr*33 + e] = s2;
                      if (colT == 0) g_s2[gr*256 + d] = s2;
                  } }
                { int e = vt & 31, c = vt >> 5;
                  #pragma unroll
                  for (int i = 0; i < 8; i++) {
                      int cc = c + i*4;
                      Bs[e*36 + cc] = W1[(size_t)(c0+cc)*256 + kb + e];
                  } }
                __syncthreads();
                #pragma unroll
                for (int e = 0; e < 32; e++) {
                    float a = As[row*33 + e];
                    float4 b4 = *(const float4*)&Bs[e*36 + cg*4];
                    a0 = fmaf(a,b4.x,a0); a1 = fmaf(a,b4.y,a1);
                    a2 = fmaf(a,b4.z,a2); a3 = fmaf(a,b4.w,a3);
                }
                __syncthreads();
            }
            int cb = c0 + cg*4;
            if (ks == 0) { a0 += b1[cb]; a1 += b1[cb+1]; a2 += b1[cb+2]; a3 += b1[cb+3]; }
            *(float4*)&g_h1p[(size_t)ks*H1_PLANE + (m0+row)*256 + cb] = make_float4(a0,a1,a2,a3);
        }
        gridbar();

        // ---------- Phase E: ffn2 + residual + LN (64 blocks, 2 rows each, 1 col/thread) ----------
        {
            bool act = bid < 64;
            int rb = (act ? bid : 0) * 2;
            float* Bs = sm;            // 256*33 = 8448
            float* As = sm + 8448;     // 2*256  = 512
            float* rs = sm + 8960;     // 16
            float* rq = sm + 8976;     // 16
            const int w = tid >> 5, lane = tid & 31;
            const int rr = w >> 3, oct = w & 7;
            const int rowr = rb + rr, col = oct*32 + lane;

            {   // stage relu(sum of 8 h1p planes): one element per thread
                int rj = tid >> 8, k = tid & 255;
                size_t off = (size_t)(rb + rj)*256 + k;
                float v = 0.f;
                #pragma unroll
                for (int p = 0; p < 8; p++) v += __ldcg(&g_h1p[(size_t)p*H1_PLANE + off]);
                As[rj*256 + k] = fmaxf(v, 0.f);
            }
            float acc = 0.f;
            for (int e0 = 0; e0 < 256; e0 += 32) {
                __syncthreads();
                for (int idx = tid; idx < 8192; idx += 512) {
                    int c = idx >> 5, e = idx & 31;
                    Bs[c*33 + e] = W2[(size_t)c*256 + e0 + e];
                }
                __syncthreads();
                #pragma unroll
                for (int e = 0; e < 32; e++)
                    acc = fmaf(As[rr*256 + e0 + e], Bs[col*33 + e], acc);
            }
            float x = acc + b2[col] + __ldcg(&g_s2[(size_t)rowr*256 + col]);
            float s = x, q = x*x;
            #pragma unroll
            for (int o = 16; o > 0; o >>= 1) {
                s += __shfl_xor_sync(0xffffffffu, s, o);
                q += __shfl_xor_sync(0xffffffffu, q, o);
            }
            __syncthreads();
            if (lane == 0) { rs[rr*8 + oct] = s; rq[rr*8 + oct] = q; }
            __syncthreads();
            float ts = 0.f, tq = 0.f;
            #pragma unroll
            for (int o = 0; o < 8; o++) { ts += rs[rr*8 + o]; tq += rq[rr*8 + o]; }
            float mean = ts * (1.f/256.f);
            float var  = tq * (1.f/256.f) - mean*mean;
            float inv  = rsqrtf(var + 1e-5f);
            if (act) {
                float y = (x - mean) * inv * lg[col] + lb[col];
                g_slots[(size_t)rowr*256 + col] = y;
                int bb = rowr >> 3, l = rowr & 7;
                outS[(size_t)((bb*16 + t)*8 + l)*256 + col] = y;
            }
        }
        gridbar();
    }
}

// ================= launcher =================
extern "C" void kernel_launch(void* const* d_in, const int* in_sizes, int n_in,
                              void* d_out, int out_size)
{
    const float* H    = (const float*)d_in[0];
    const float* eps  = (const float*)d_in[1];
    const float* mu   = (const float*)d_in[2];
    const float* ls   = (const float*)d_in[3];
    const float* Wq   = (const float*)d_in[4];
    const float* bq   = (const float*)d_in[5];
    const float* Wk   = (const float*)d_in[6];
    // d_in[7] = bk: row-constant in logits, cancels in softmax — provably unused.
    const float* Wv   = (const float*)d_in[8];
    const float* bv   = (const float*)d_in[9];
    const float* W_ih = (const float*)d_in[10];
    const float* b_ih = (const float*)d_in[11];
    const float* W_hh = (const float*)d_in[12];
    const float* b_hh = (const float*)d_in[13];
    const float* W1   = (const float*)d_in[14];
    const float* b1   = (const float*)d_in[15];
    const float* W2   = (const float*)d_in[16];
    const float* b2   = (const float*)d_in[17];
    const float* lng  = (const float*)d_in[18];
    const float* lnb  = (const float*)d_in[19];

    float* outS = (float*)d_out;
    float* outB = outS + S_ELEMS;

    pre_misc<<<952, 256>>>(eps, mu, ls, W_hh, bq, Wk, b_hh, W_ih, bv, b_ih);
    pre_gemm<<<dim3(8, 32), 256>>>(Wq, Wk, W_ih, Wv);
    mega_kernel<<<NB, 512>>>(H, W1, b1, W2, b2, lng, lnb, outS, outB);
}